// round 1
// baseline (speedup 1.0000x reference)
#include <cuda_runtime.h>

#define SEQ_LEN   8192
#define STATE_LEN 4096
#define T_DIM     1024
#define THREADS   256
#define ITERS     8          // 8 iterations x 4 floats x 256 threads = 8192

__global__ __launch_bounds__(THREADS)
void attn_time_softmax_kernel(const int* __restrict__ his,
                              const int* __restrict__ cur,
                              const float* __restrict__ tsm,
                              float* __restrict__ out)
{
    __shared__ float row[T_DIM];     // the gathered time_sim_mat row (4 KB)
    __shared__ float red_max[THREADS / 32];
    __shared__ float red_sum[THREADS / 32];

    const int tid = threadIdx.x;
    const int i   = blockIdx.x;

    // ---- load row cur[i] of time_sim_mat into smem (vectorized, 4 KB) ----
    const int c = cur[i];                       // broadcast LDG (L1/L2 hit)
    {
        const float4* src = reinterpret_cast<const float4*>(tsm + (size_t)c * T_DIM);
        reinterpret_cast<float4*>(row)[tid] = src[tid];   // 256 * 16B = 4 KB
    }
    __syncthreads();

    // ---- phase 1: gather into registers, track thread-local max ----
    float e[ITERS * 4];
    float m = -INFINITY;
    const int4* his4 = reinterpret_cast<const int4*>(his);
    #pragma unroll
    for (int it = 0; it < ITERS; it++) {
        int4 h = his4[it * THREADS + tid];      // coalesced, L1-resident after warmup
        float a = row[h.x];
        float b = row[h.y];
        float g = row[h.z];
        float d = row[h.w];
        e[it * 4 + 0] = a;
        e[it * 4 + 1] = b;
        e[it * 4 + 2] = g;
        e[it * 4 + 3] = d;
        m = fmaxf(m, fmaxf(fmaxf(a, b), fmaxf(g, d)));
    }

    // ---- block max reduction ----
    #pragma unroll
    for (int off = 16; off; off >>= 1)
        m = fmaxf(m, __shfl_xor_sync(0xffffffff, m, off));
    if ((tid & 31) == 0) red_max[tid >> 5] = m;
    __syncthreads();
    float bm = red_max[0];
    #pragma unroll
    for (int w = 1; w < THREADS / 32; w++) bm = fmaxf(bm, red_max[w]);

    // ---- phase 2: exp once (kept in registers), thread-local sum ----
    float s = 0.0f;
    #pragma unroll
    for (int k = 0; k < ITERS * 4; k++) {
        e[k] = __expf(e[k] - bm);
        s += e[k];
    }

    // ---- block sum reduction ----
    #pragma unroll
    for (int off = 16; off; off >>= 1)
        s += __shfl_xor_sync(0xffffffff, s, off);
    if ((tid & 31) == 0) red_sum[tid >> 5] = s;
    __syncthreads();
    float bs = 0.0f;
    #pragma unroll
    for (int w = 0; w < THREADS / 32; w++) bs += red_sum[w];
    const float inv = 1.0f / bs;

    // ---- phase 3: normalize + coalesced float4 stores ----
    float4* o = reinterpret_cast<float4*>(out + (size_t)i * SEQ_LEN);
    #pragma unroll
    for (int it = 0; it < ITERS; it++) {
        float4 v;
        v.x = e[it * 4 + 0] * inv;
        v.y = e[it * 4 + 1] * inv;
        v.z = e[it * 4 + 2] * inv;
        v.w = e[it * 4 + 3] * inv;
        o[it * THREADS + tid] = v;
    }
}

extern "C" void kernel_launch(void* const* d_in, const int* in_sizes, int n_in,
                              void* d_out, int out_size)
{
    const int*   his = (const int*)d_in[0];    // [8192] int32
    const int*   cur = (const int*)d_in[1];    // [4096] int32
    const float* tsm = (const float*)d_in[2];  // [1024*1024] fp32
    float*       out = (float*)d_out;          // [4096*8192] fp32

    attn_time_softmax_kernel<<<STATE_LEN, THREADS>>>(his, cur, tsm, out);
}